// round 16
// baseline (speedup 1.0000x reference)
#include <cuda_runtime.h>

#define NBOX 4096
#define IMG_H 360
#define IMG_W 1200
#define BEV_H 700
#define BEV_W 800

// ---------------- device scratch (no allocations allowed) ----------------
__device__ __align__(16) float  g_conv_img[IMG_H * IMG_W];
__device__ __align__(16) float  g_conv_bev[BEV_H * BEV_W];
__device__ __align__(16) float  g_fused[NBOX * 9];
__device__ __align__(16) float  g_reg[NBOX * 6];
__device__ __align__(16) float  g_obj[NBOX * 2];
__device__ __align__(16) float  g_bev[NBOX * 4];
__device__ __align__(16) float  g_key[NBOX];
__device__ __align__(16) int    g_order[NBOX];
__device__ __align__(16) float  g_sbev[NBOX * 4];
__device__ __align__(16) unsigned long long g_mask[NBOX * 64];

// correctly-rounded fp32 exp (== glibc expf)
__device__ __forceinline__ float exp_cr(float x) {
    return (float)exp((double)x);
}

// ---- 1x1 conv (32->1): unfused mul+reduce, sequential c, +bias, relu -------
__global__ void k_conv(const float* __restrict__ in, const float* __restrict__ w,
                       const float* __restrict__ b, int hw4, int which) {
    int p = blockIdx.x * blockDim.x + threadIdx.x;
    if (p >= hw4) return;
    float* out = which ? g_conv_bev : g_conv_img;
    const float4* in4 = (const float4*)in;
    float bb = __ldg(&b[0]);
    float ax = 0.f, ay = 0.f, az = 0.f, aw = 0.f;
#pragma unroll
    for (int c = 0; c < 32; c++) {
        float wc = __ldg(&w[c]);
        float4 v = __ldg(&in4[(long)c * hw4 + p]);
        ax = __fadd_rn(ax, __fmul_rn(v.x, wc));
        ay = __fadd_rn(ay, __fmul_rn(v.y, wc));
        az = __fadd_rn(az, __fmul_rn(v.z, wc));
        aw = __fadd_rn(aw, __fmul_rn(v.w, wc));
    }
    float4 o;
    o.x = fmaxf(__fadd_rn(ax, bb), 0.f);
    o.y = fmaxf(__fadd_rn(ay, bb), 0.f);
    o.z = fmaxf(__fadd_rn(az, bb), 0.f);
    o.w = fmaxf(__fadd_rn(aw, bb), 0.f);
    ((float4*)out)[p] = o;
}

// ---- ROI align: unfused coords, bilinear unfused; steps via RECIPROCAL -----
// XLA algsimp: (k+0.5)/6 -> (k+0.5) * fp32(1/6). Differs by 1 ulp for k=2,3,5.
__device__ __forceinline__ float roi_sample(const float* __restrict__ f, int H, int W,
                                            float ax1, float ay1, float ax2, float ay2,
                                            int by, int bx) {
    const float RCP6 = 0.16666667f;   // fp32(1/6) = 0x3E2AAAAB
    float x1 = __fsub_rn(ax1, 0.5f), y1 = __fsub_rn(ay1, 0.5f);
    float rw = __fsub_rn(ax2, ax1),  rh = __fsub_rn(ay2, ay1);
    float s = 0.f;
#pragma unroll
    for (int sy = 0; sy < 2; sy++) {
        float stepy = __fmul_rn(__fadd_rn((float)(by * 2 + sy), 0.5f), RCP6);
        float y = __fadd_rn(y1, __fmul_rn(rh, stepy));
        y = fminf(fmaxf(y, 0.f), (float)(H - 1));
        float y0f = floorf(y);
        int y0 = (int)y0f;
        int yy1 = min(y0 + 1, H - 1);
        float ly = __fsub_rn(y, y0f);
        float oly = __fsub_rn(1.0f, ly);
        const float* r0 = f + (long)y0 * W;
        const float* r1 = f + (long)yy1 * W;
#pragma unroll
        for (int sx = 0; sx < 2; sx++) {
            float stepx = __fmul_rn(__fadd_rn((float)(bx * 2 + sx), 0.5f), RCP6);
            float x = __fadd_rn(x1, __fmul_rn(rw, stepx));
            x = fminf(fmaxf(x, 0.f), (float)(W - 1));
            float x0f = floorf(x);
            int x0 = (int)x0f;
            int xx1 = min(x0 + 1, W - 1);
            float lx = __fsub_rn(x, x0f);
            float olx = __fsub_rn(1.0f, lx);
            float v00 = __ldg(&r0[x0]);
            float v01 = __ldg(&r0[xx1]);
            float v10 = __ldg(&r1[x0]);
            float v11 = __ldg(&r1[xx1]);
            float t1 = __fmul_rn(__fmul_rn(v00, oly), olx);
            float t2 = __fmul_rn(__fmul_rn(v01, oly), lx);
            float t3 = __fmul_rn(__fmul_rn(v10, ly), olx);
            float t4 = __fmul_rn(__fmul_rn(v11, ly), lx);
            float v = __fadd_rn(__fadd_rn(__fadd_rn(t1, t2), t3), t4);
            s = __fadd_rn(s, v);
        }
    }
    return __fmul_rn(s, 0.25f);   // mean over 2x2 samples (exact /4)
}

__global__ void k_roi(const float* __restrict__ a_img, const float* __restrict__ a_bev,
                      const float* __restrict__ im, const float* __restrict__ bm) {
    int gid = blockIdx.x * blockDim.x + threadIdx.x;
    if (gid >= NBOX * 9) return;
    int r = gid / 9, bin = gid - r * 9;
    int by = bin / 3, bx = bin - by * 3;
    float mi = __ldg(&im[0]), mb = __ldg(&bm[0]);
    const float* ri = a_img + (long)r * 5;
    const float* rb = a_bev + (long)r * 5;
    float vi = roi_sample(g_conv_img, IMG_H, IMG_W,
                          __ldg(&ri[1]), __ldg(&ri[2]), __ldg(&ri[3]), __ldg(&ri[4]), by, bx);
    float vb = roi_sample(g_conv_bev, BEV_H, BEV_W,
                          __ldg(&rb[1]), __ldg(&rb[2]), __ldg(&rb[3]), __ldg(&rb[4]), by, bx);
    vi = __fmul_rn(mi, vi);
    vb = __fmul_rn(mb, vb);
    g_fused[gid] = __fdiv_rn(__fadd_rn(vi, vb), __fadd_rn(mi, mb));
}

// ------ MLP: fp32 sequential-k FUSED FMA chains from 0, bias after -----------
__global__ __launch_bounds__(256) void k_mlp(
    const float* __restrict__ W1, const float* __restrict__ b1,
    const float* __restrict__ W2, const float* __restrict__ b2,
    const float* __restrict__ Wo, const float* __restrict__ bo,
    const float* __restrict__ Wf, const float* __restrict__ bf,
    const float* __restrict__ fa) {
    __shared__ float sh_f[32][12];
    __shared__ __align__(16) float sh_h[32][260];
    __shared__ float sh_out[32][8];
    int t = threadIdx.x;
    int r0 = blockIdx.x * 32;

    for (int i = t; i < 32 * 9; i += 256) {
        int r = i / 9, k = i - r * 9;
        sh_f[r][k] = g_fused[(r0 + r) * 9 + k];
    }
    __syncthreads();

    // ---- layer 1: column t; dot from 0 ascending k, then +b1, relu ----
    {
        float w1c[9];
#pragma unroll
        for (int k = 0; k < 9; k++) w1c[k] = __ldg(&W1[k * 256 + t]);
        float bb1 = __ldg(&b1[t]);
        for (int r = 0; r < 32; r++) {
            float a = 0.f;
#pragma unroll
            for (int k = 0; k < 9; k++) a = __fmaf_rn(sh_f[r][k], w1c[k], a);
            sh_h[r][t] = fmaxf(__fadd_rn(a, bb1), 0.f);
        }
    }
    __syncthreads();

    // ---- layer 2: dot from 0 ascending s, then +b2, relu ----
    {
        float acc[32];
#pragma unroll
        for (int r = 0; r < 32; r++) acc[r] = 0.f;
        for (int s = 0; s < 256; s += 4) {
            float w0 = __ldg(&W2[(s + 0) * 256 + t]);
            float w1 = __ldg(&W2[(s + 1) * 256 + t]);
            float w2 = __ldg(&W2[(s + 2) * 256 + t]);
            float w3 = __ldg(&W2[(s + 3) * 256 + t]);
#pragma unroll
            for (int r = 0; r < 32; r++) {
                float4 h = *(const float4*)&sh_h[r][s];
                float a = acc[r];
                a = __fmaf_rn(h.x, w0, a);
                a = __fmaf_rn(h.y, w1, a);
                a = __fmaf_rn(h.z, w2, a);
                a = __fmaf_rn(h.w, w3, a);
                acc[r] = a;
            }
        }
        float bb2 = __ldg(&b2[t]);
        __syncthreads();
#pragma unroll
        for (int r = 0; r < 32; r++) sh_h[r][t] = fmaxf(__fadd_rn(acc[r], bb2), 0.f);
    }
    __syncthreads();

    // ---- heads: 32 rois x 8 outputs; dot from 0 ascending s, then +bias ----
    {
        int r = t >> 3, o = t & 7;
        float a = 0.f;
        for (int s = 0; s < 256; s++) {
            float w = (o < 2) ? __ldg(&Wo[s * 2 + o]) : __ldg(&Wf[s * 6 + (o - 2)]);
            a = __fmaf_rn(sh_h[r][s], w, a);
        }
        float bias = (o < 2) ? __ldg(&bo[o]) : __ldg(&bf[o - 2]);
        float af = __fadd_rn(a, bias);
        sh_out[r][o] = af;
        if (o < 2) g_obj[(r0 + r) * 2 + o] = af;
    }
    __syncthreads();

    // ---- decode (unfused fp32) + bev project + fp32 softmax score ----------
    if (t < 32) {
        int gr = r0 + t;
        const float* f6 = fa + (long)gr * 6;
        float fa0 = __ldg(&f6[0]), fa1 = __ldg(&f6[1]), fa2 = __ldg(&f6[2]);
        float fa3 = __ldg(&f6[3]), fa4 = __ldg(&f6[4]), fa5 = __ldg(&f6[5]);
        float o0 = sh_out[t][2], o1 = sh_out[t][3], o2 = sh_out[t][4];
        float o3 = sh_out[t][5], o4 = sh_out[t][6], o5 = sh_out[t][7];
        float cx = __fadd_rn(fa0, __fmul_rn(o0, fa3));
        float cy = __fadd_rn(fa1, __fmul_rn(o1, fa4));
        float cz = __fadd_rn(fa2, __fmul_rn(o2, fa5));
        float dx = __fmul_rn(fa3, exp_cr(o3));
        float dy = __fmul_rn(fa4, exp_cr(o4));
        float dz = __fmul_rn(fa5, exp_cr(o5));
        g_reg[gr * 6 + 0] = cx; g_reg[gr * 6 + 1] = cy; g_reg[gr * 6 + 2] = cz;
        g_reg[gr * 6 + 3] = dx; g_reg[gr * 6 + 4] = dy; g_reg[gr * 6 + 5] = dz;
        float bx = __fsub_rn(cx, -40.0f);   // x - X_MIN
        float bz = __fsub_rn(cz, 0.0f);     // z - Z_MIN
        g_bev[gr * 4 + 0] = __fsub_rn(bx, __fmul_rn(dx, 0.5f));
        g_bev[gr * 4 + 1] = __fsub_rn(bz, __fmul_rn(dz, 0.5f));
        g_bev[gr * 4 + 2] = __fadd_rn(bx, __fmul_rn(dx, 0.5f));
        g_bev[gr * 4 + 3] = __fadd_rn(bz, __fmul_rn(dz, 0.5f));
        // score = softmax([l0,l1])[1], fp32 op-by-op
        float l0 = sh_out[t][0], l1 = sh_out[t][1];
        float m  = fmaxf(l0, l1);
        float e0 = exp_cr(__fsub_rn(l0, m));
        float e1 = exp_cr(__fsub_rn(l1, m));
        g_key[gr] = __fdiv_rn(e1, __fadd_rn(e0, e1));
    }
}

// ---------------- bitonic sort 4096 by (fp32 score desc, idx asc) ------------
__global__ __launch_bounds__(1024) void k_sort() {
    __shared__ float sk[4096];
    __shared__ int   si[4096];
    int t = threadIdx.x;
    for (int i = t; i < 4096; i += 1024) { sk[i] = g_key[i]; si[i] = i; }
    __syncthreads();
    for (int k = 2; k <= 4096; k <<= 1) {
        for (int j = k >> 1; j > 0; j >>= 1) {
            for (int i = t; i < 4096; i += 1024) {
                int ixj = i ^ j;
                if (ixj > i) {
                    float ka = sk[i], kb = sk[ixj];
                    int ia = si[i], ib = si[ixj];
                    bool before = (ka > kb) || (ka == kb && ia < ib);
                    bool dirDesc = ((i & k) == 0);
                    bool doswap = dirDesc ? (!before) : before;
                    if (doswap) {
                        sk[i] = kb; sk[ixj] = ka;
                        si[i] = ib; si[ixj] = ia;
                    }
                }
            }
            __syncthreads();
        }
    }
    for (int i = t; i < 4096; i += 1024) {
        int oi = si[i];
        g_order[i] = oi;
        float4 b = *(const float4*)&g_bev[oi * 4];
        *(float4*)&g_sbev[i * 4] = b;
    }
}

// ---------------- IoU suppression bitmask (sorted order) ---------------------
__global__ __launch_bounds__(64) void k_mask() {
    int by = blockIdx.y, bx = blockIdx.x;
    if (bx < by) return;
    __shared__ float4 cb[64];
    int t = threadIdx.x;
    cb[t] = *(const float4*)&g_sbev[(bx * 64 + t) * 4];
    __syncthreads();
    int i = by * 64 + t;
    float4 a = *(const float4*)&g_sbev[i * 4];
    float areaA = __fmul_rn(__fsub_rn(a.z, a.x), __fsub_rn(a.w, a.y));
    unsigned long long bits = 0ull;
    int start = (bx == by) ? (t + 1) : 0;
    for (int j = start; j < 64; j++) {
        float4 b = cb[j];
        float w = fmaxf(__fsub_rn(fminf(a.z, b.z), fmaxf(a.x, b.x)), 0.f);
        float h = fmaxf(__fsub_rn(fminf(a.w, b.w), fmaxf(a.y, b.y)), 0.f);
        float inter = __fmul_rn(w, h);
        float areaB = __fmul_rn(__fsub_rn(b.z, b.x), __fsub_rn(b.w, b.y));
        float den = __fadd_rn(__fsub_rn(__fadd_rn(areaA, areaB), inter), 1e-8f);
        float iou = __fdiv_rn(inter, den);
        if (iou > 0.8f) bits |= (1ull << j);
    }
    g_mask[(size_t)i * 64 + bx] = bits;
}

// ---------------- greedy NMS + stable partition + output ---------------------
__global__ __launch_bounds__(1024) void k_gather(float* __restrict__ out) {
    __shared__ unsigned long long remv[64];
    __shared__ unsigned long long keepb[64];
    __shared__ unsigned long long diag[64];
    __shared__ int pref[65];
    int t = threadIdx.x;
    if (t < 64) remv[t] = 0ull;
    __syncthreads();
    for (int c = 0; c < 64; c++) {
        if (t < 64) diag[t] = g_mask[(size_t)((c << 6) + t) * 64 + c];
        __syncthreads();
        if (t == 0) {
            unsigned long long local = remv[c], kb = 0ull;
            for (int b = 0; b < 64; b++) {
                if (!((local >> b) & 1ull)) {
                    kb |= (1ull << b);
                    local |= diag[b];
                }
            }
            keepb[c] = kb;
        }
        __syncthreads();
        unsigned long long kb = keepb[c];
        int w = c + 1 + (t & 63);
        int bg = t >> 6;
        if (w < 64 && kb) {
            unsigned long long v = 0ull;
#pragma unroll
            for (int b0 = 0; b0 < 4; b0++) {
                int b = bg + b0 * 16;
                if ((kb >> b) & 1ull) v |= g_mask[(size_t)((c << 6) + b) * 64 + w];
            }
            if (v) atomicOr(&remv[w], v);
        }
        __syncthreads();
    }
    if (t == 0) {
        int a = 0;
        for (int c = 0; c < 64; c++) { pref[c] = a; a += __popcll(keepb[c]); }
        pref[64] = a;
    }
    __syncthreads();
    int total = pref[64];
    for (int i = t; i < 4096; i += 1024) {
        int c = i >> 6, b = i & 63;
        unsigned long long kb = keepb[c];
        unsigned long long below = b ? ((1ull << b) - 1ull) : 0ull;
        int keptBefore = pref[c] + __popcll(kb & below);
        bool isk = (kb >> b) & 1ull;
        int rank = isk ? keptBefore : (total + (i - keptBefore));
        if (rank < 1024) {
            int oi = g_order[i];
            float* dst = out + (long)rank * 8;
            const float* rg = g_reg + (long)oi * 6;
            dst[0] = rg[0]; dst[1] = rg[1]; dst[2] = rg[2];
            dst[3] = rg[3]; dst[4] = rg[4]; dst[5] = rg[5];
            dst[6] = g_obj[oi * 2 + 0];
            dst[7] = g_obj[oi * 2 + 1];
        }
    }
}

// ---------------- launch ----------------
extern "C" void kernel_launch(void* const* d_in, const int* in_sizes, int n_in,
                              void* d_out, int out_size) {
    const float* img_map = (const float*)d_in[0];
    const float* bev_map = (const float*)d_in[1];
    const float* a_img   = (const float*)d_in[2];
    const float* a_bev   = (const float*)d_in[3];
    const float* fa      = (const float*)d_in[4];
    const float* im      = (const float*)d_in[5];
    const float* bm      = (const float*)d_in[6];
    const float* w_img   = (const float*)d_in[7];
    const float* b_img   = (const float*)d_in[8];
    const float* w_bev   = (const float*)d_in[9];
    const float* b_bev   = (const float*)d_in[10];
    const float* W1      = (const float*)d_in[11];
    const float* b1      = (const float*)d_in[12];
    const float* W2      = (const float*)d_in[13];
    const float* b2      = (const float*)d_in[14];
    const float* Wo      = (const float*)d_in[15];
    const float* bo      = (const float*)d_in[16];
    const float* Wf      = (const float*)d_in[17];
    const float* bf      = (const float*)d_in[18];
    float* out = (float*)d_out;

    int img_hw4 = (IMG_H * IMG_W) / 4;   // 108000
    int bev_hw4 = (BEV_H * BEV_W) / 4;   // 140000
    k_conv<<<(img_hw4 + 255) / 256, 256>>>(img_map, w_img, b_img, img_hw4, 0);
    k_conv<<<(bev_hw4 + 255) / 256, 256>>>(bev_map, w_bev, b_bev, bev_hw4, 1);
    k_roi<<<(NBOX * 9 + 255) / 256, 256>>>(a_img, a_bev, im, bm);
    k_mlp<<<128, 256>>>(W1, b1, W2, b2, Wo, bo, Wf, bf, fa);
    k_sort<<<1, 1024>>>();
    dim3 mg(64, 64);
    k_mask<<<mg, 64>>>();
    k_gather<<<1, 1024>>>(out);
}